// round 1
// baseline (speedup 1.0000x reference)
#include <cuda_runtime.h>
#include <math.h>

#define BB 8
#define CC 1024
#define TT 1024
#define HH 16
#define DD 64
#define CT (CC*TT)

// ---------------- scratch (device globals: allocation-free) ----------------
__device__ float g_q[BB*CC*TT];
__device__ float g_k[BB*CC*TT];
__device__ float g_v[BB*CC*TT];
__device__ float g_attn[BB*CC*TT];

// ---------------- GEMM: Y[b][m][n] = sum_c W[m][c] * X[b][c][n] + bias[m] --
// 128x128 tile, BK=16, 256 threads, 8x8 per thread micro-tile.
__global__ __launch_bounds__(256) void gemm_bias_kernel(
    const float* __restrict__ W, const float* __restrict__ bias,
    const float* __restrict__ X, float* __restrict__ Y)
{
    __shared__ float Ws[16][128];
    __shared__ float Xs[16][128];
    const int b  = blockIdx.z;
    const float* Xb = X + (long)b*CT;
    float*       Yb = Y + (long)b*CT;
    const int m0 = blockIdx.y*128, n0 = blockIdx.x*128;
    const int tid = threadIdx.x;
    const int tm = (tid>>4)*8, tn = (tid&15)*8;

    float acc[8][8];
    #pragma unroll
    for (int i = 0; i < 8; i++)
        #pragma unroll
        for (int j = 0; j < 8; j++) acc[i][j] = 0.f;

    for (int kt = 0; kt < CC; kt += 16) {
        // W tile: load rows (coalesced), store transposed Ws[k][m]
        #pragma unroll
        for (int i = 0; i < 2; i++) {
            int f = tid + i*256;           // float4 id in [0,512)
            int m = f>>2, kq = (f&3)*4;
            float4 w = *(const float4*)(W + (long)(m0+m)*CC + kt + kq);
            Ws[kq+0][m] = w.x; Ws[kq+1][m] = w.y;
            Ws[kq+2][m] = w.z; Ws[kq+3][m] = w.w;
        }
        // X tile: straight copy (coalesced)
        #pragma unroll
        for (int i = 0; i < 2; i++) {
            int f = tid + i*256;
            int k = f>>5, n4 = (f&31)*4;
            *(float4*)(&Xs[k][n4]) = *(const float4*)(Xb + (long)(kt+k)*TT + n0 + n4);
        }
        __syncthreads();
        #pragma unroll
        for (int k = 0; k < 16; k++) {
            float a[8], bb2[8];
            *(float4*)(a)     = *(const float4*)(&Ws[k][tm]);
            *(float4*)(a+4)   = *(const float4*)(&Ws[k][tm+4]);
            *(float4*)(bb2)   = *(const float4*)(&Xs[k][tn]);
            *(float4*)(bb2+4) = *(const float4*)(&Xs[k][tn+4]);
            #pragma unroll
            for (int i = 0; i < 8; i++)
                #pragma unroll
                for (int j = 0; j < 8; j++)
                    acc[i][j] += a[i]*bb2[j];
        }
        __syncthreads();
    }
    #pragma unroll
    for (int i = 0; i < 8; i++) {
        float bv = bias[m0+tm+i];
        #pragma unroll
        for (int j = 0; j < 8; j += 4) {
            float4 r = make_float4(acc[i][j]+bv, acc[i][j+1]+bv,
                                   acc[i][j+2]+bv, acc[i][j+3]+bv);
            *(float4*)(Yb + (long)(m0+tm+i)*TT + n0+tn + j) = r;
        }
    }
}

// ---------------- RoPE (in place, [B,C,T] layout) --------------------------
// rotate channels (h*64 + i, h*64 + i + 16), i in [0,16)
__global__ void rope_kernel(float* __restrict__ data)
{
    int idx = blockIdx.x*blockDim.x + threadIdx.x;   // B*H*16*T threads
    int t  = idx & (TT-1);
    int i  = (idx>>10) & 15;
    int bh = idx>>14;                                 // b*H + h in [0,128)
    long base = (long)bh*DD*TT + (long)i*TT + t;
    float x1 = data[base];
    float x2 = data[base + 16*TT];
    float theta = powf(10000.f, -(float)i/16.f);
    float ang = (float)t * theta;
    float cs = cosf(ang), sn = sinf(ang);
    data[base]         = x1*cs - x2*sn;
    data[base + 16*TT] = x2*cs + x1*sn;
}

// ---------------- attention ------------------------------------------------
// 1 block = (head bh, 128 q rows), 128 threads = 1 q-row each.
// Flash-style online softmax over K tiles of 32.
#define BKK 32
__global__ __launch_bounds__(128) void attn_kernel(
    const int* __restrict__ mask, float* __restrict__ outp)
{
    __shared__ float Ks[BKK][68];     // [j][d], pad 68 keeps float4 rows aligned
    __shared__ float Vs[BKK][68];
    __shared__ float Ss[BKK][128];    // per-row scores for this tile
    __shared__ float bias_tab[TT];

    const int tid = threadIdx.x;
    const int bh  = blockIdx.y;
    const int b   = bh >> 4;
    const int qt  = blockIdx.x*128 + tid;
    const float* qp = g_q + (long)b*CT + (long)(bh & 15)*DD*TT;
    const float* kp = g_k + (long)b*CT + (long)(bh & 15)*DD*TT;
    const float* vp = g_v + (long)b*CT + (long)(bh & 15)*DD*TT;

    for (int i = tid; i < TT; i += 128) bias_tab[i] = -log1pf((float)i);

    float4 q4[16], o4[16];
    #pragma unroll
    for (int d4 = 0; d4 < 16; d4++) {
        q4[d4].x = qp[(long)(4*d4+0)*TT + qt];
        q4[d4].y = qp[(long)(4*d4+1)*TT + qt];
        q4[d4].z = qp[(long)(4*d4+2)*TT + qt];
        q4[d4].w = qp[(long)(4*d4+3)*TT + qt];
        o4[d4] = make_float4(0.f,0.f,0.f,0.f);
    }
    float mrun = -1e30f, lrun = 0.f;
    __syncthreads();   // bias_tab ready

    for (int kt0 = 0; kt0 < TT; kt0 += BKK) {
        // load K/V tiles [j][d] (coalesced over j)
        #pragma unroll
        for (int i = 0; i < 4; i++) {
            int f = tid + i*128;          // float4 id in [0,512)
            int d = f>>3, j4 = (f&7)*4;
            float4 kv = *(const float4*)(kp + (long)d*TT + kt0 + j4);
            Ks[j4+0][d]=kv.x; Ks[j4+1][d]=kv.y; Ks[j4+2][d]=kv.z; Ks[j4+3][d]=kv.w;
            float4 vv = *(const float4*)(vp + (long)d*TT + kt0 + j4);
            Vs[j4+0][d]=vv.x; Vs[j4+1][d]=vv.y; Vs[j4+2][d]=vv.z; Vs[j4+3][d]=vv.w;
        }
        __syncthreads();

        // S = q . K^T * 0.125 + bias, track tile max
        float tmax = -1e30f;
        for (int j = 0; j < BKK; j++) {
            const float4* krow = (const float4*)(&Ks[j][0]);
            float4 acc = make_float4(0.f,0.f,0.f,0.f);
            #pragma unroll
            for (int d4 = 0; d4 < 16; d4++) {
                float4 kk = krow[d4];
                acc.x += q4[d4].x*kk.x;
                acc.y += q4[d4].y*kk.y;
                acc.z += q4[d4].z*kk.z;
                acc.w += q4[d4].w*kk.w;
            }
            float s = ((acc.x+acc.y)+(acc.z+acc.w))*0.125f;
            int tk = kt0 + j;
            s += bias_tab[abs(qt - tk)];
            if (mask[(long)b*TT + tk] == 0) s = -10000.f;
            tmax = fmaxf(tmax, s);
            Ss[j][tid] = s;
        }

        // online softmax rescale + P@V accumulate
        float mnew  = fmaxf(mrun, tmax);
        float scale = __expf(mrun - mnew);
        lrun *= scale;
        #pragma unroll
        for (int d4 = 0; d4 < 16; d4++) {
            o4[d4].x *= scale; o4[d4].y *= scale;
            o4[d4].z *= scale; o4[d4].w *= scale;
        }
        for (int j = 0; j < BKK; j++) {
            float p = __expf(Ss[j][tid] - mnew);
            lrun += p;
            const float4* vrow = (const float4*)(&Vs[j][0]);
            #pragma unroll
            for (int d4 = 0; d4 < 16; d4++) {
                float4 vv = vrow[d4];
                o4[d4].x += p*vv.x; o4[d4].y += p*vv.y;
                o4[d4].z += p*vv.z; o4[d4].w += p*vv.w;
            }
        }
        mrun = mnew;
        __syncthreads();
    }

    float inv = 1.f/lrun;
    float* op = outp + (long)b*CT + (long)(bh & 15)*DD*TT;
    #pragma unroll
    for (int d4 = 0; d4 < 16; d4++) {
        op[(long)(4*d4+0)*TT + qt] = o4[d4].x*inv;
        op[(long)(4*d4+1)*TT + qt] = o4[d4].y*inv;
        op[(long)(4*d4+2)*TT + qt] = o4[d4].z*inv;
        op[(long)(4*d4+3)*TT + qt] = o4[d4].w*inv;
    }
}

// ---------------- launch ---------------------------------------------------
extern "C" void kernel_launch(void* const* d_in, const int* in_sizes, int n_in,
                              void* d_out, int out_size)
{
    const float* x    = (const float*)d_in[0];
    const float* ctx  = (const float*)d_in[1];
    const int*   mask = (const int*)  d_in[2];
    const float* Wq   = (const float*)d_in[3];
    const float* bq   = (const float*)d_in[4];
    const float* Wk   = (const float*)d_in[5];
    const float* bk   = (const float*)d_in[6];
    const float* Wv   = (const float*)d_in[7];
    const float* bv   = (const float*)d_in[8];
    const float* Wo   = (const float*)d_in[9];
    const float* bo   = (const float*)d_in[10];
    float* out = (float*)d_out;

    float *q, *k, *v, *attn;
    cudaGetSymbolAddress((void**)&q,    g_q);
    cudaGetSymbolAddress((void**)&k,    g_k);
    cudaGetSymbolAddress((void**)&v,    g_v);
    cudaGetSymbolAddress((void**)&attn, g_attn);

    dim3 gg(TT/128, CC/128, BB);
    gemm_bias_kernel<<<gg, 256>>>(Wq, bq, x,   q);
    gemm_bias_kernel<<<gg, 256>>>(Wk, bk, ctx, k);
    gemm_bias_kernel<<<gg, 256>>>(Wv, bv, ctx, v);

    int nrope = BB*HH*16*TT;            // one thread per rotated pair
    rope_kernel<<<nrope/256, 256>>>(q);
    rope_kernel<<<nrope/256, 256>>>(k);

    dim3 ga(TT/128, BB*HH);
    attn_kernel<<<ga, 128>>>(mask, attn);

    gemm_bias_kernel<<<gg, 256>>>(Wo, bo, attn, out);
}